// round 1
// baseline (speedup 1.0000x reference)
#include <cuda_runtime.h>
#include <cstdint>
#include <cstddef>

// Problem constants
#define S_LEN 2048
#define DM    1024
#define NH    16
#define DEPTH 64
#define BATCH 2
#define BH    (BATCH * NH)                       // 32
#define MROWS (BATCH * S_LEN)                    // 4096
#define OUT_ELEMS  ((size_t)BATCH * S_LEN * DM)          // 4194304
#define ATTN_ELEMS ((size_t)BH * S_LEN * S_LEN)          // 134217728

// ---- device scratch (static; allocation-free rule) ----
__device__ float g_q[BH * S_LEN * DEPTH];     // [z=b*16+h][s][d]
__device__ float g_k[BH * S_LEN * DEPTH];
__device__ float g_v[BH * S_LEN * DEPTH];
__device__ float g_ctx[MROWS * DM];           // [b*S+s][h*64+d]
__device__ float g_out[MROWS * DM];           // fallback out if not in d_out
__device__ float g_attn[BH * S_LEN * S_LEN];  // fallback attn if not in d_out

// ============================================================
// GEMM + bias: C[M,N] = A[M,K] @ W[K,N] + bias[N]
// mode 0: write row-major to C (C==nullptr -> g_out)
// mode 1/2/3: write head-split into g_q / g_k / g_v
// asel 0: A param; asel 1: A = g_ctx
// 128x128 block tile, BK=16, 256 threads, 8x8 per thread.
// ============================================================
__global__ __launch_bounds__(256) void gemm_bias_kernel(
    const float* __restrict__ A, const float* __restrict__ W,
    const float* __restrict__ bias, float* __restrict__ C,
    int M, int N, int K, int mode, int asel)
{
    __shared__ float As[16][128];   // [k][m] transposed
    __shared__ float Bs[16][128];   // [k][n]

    if (asel == 1) A = g_ctx;
    float* Cout = C;
    if (mode == 0 && Cout == nullptr) Cout = g_out;

    const int tid = threadIdx.x;
    const int br = blockIdx.y, bc = blockIdx.x;
    const int ty = tid >> 4, tx = tid & 15;

    const int arow = tid >> 2;            // 0..63
    const int acol = (tid & 3) << 2;      // 0,4,8,12
    const int brow = tid >> 5;            // 0..7
    const int bcol = (tid & 31) << 2;     // 0..124

    float acc[8][8];
#pragma unroll
    for (int i = 0; i < 8; i++)
#pragma unroll
        for (int j = 0; j < 8; j++) acc[i][j] = 0.0f;

    const float* Ab = A + (size_t)br * 128 * K;
    const float* Wb = W + (size_t)bc * 128;

    for (int k0 = 0; k0 < K; k0 += 16) {
#pragma unroll
        for (int p = 0; p < 2; p++) {
            float4 a = *reinterpret_cast<const float4*>(
                Ab + (size_t)(arow + p * 64) * K + k0 + acol);
            As[acol + 0][arow + p * 64] = a.x;
            As[acol + 1][arow + p * 64] = a.y;
            As[acol + 2][arow + p * 64] = a.z;
            As[acol + 3][arow + p * 64] = a.w;
            float4 b = *reinterpret_cast<const float4*>(
                Wb + (size_t)(k0 + brow + p * 8) * N + bcol);
            *reinterpret_cast<float4*>(&Bs[brow + p * 8][bcol]) = b;
        }
        __syncthreads();
#pragma unroll
        for (int kk = 0; kk < 16; kk++) {
            float ra[8], rb[8];
#pragma unroll
            for (int i = 0; i < 8; i++) ra[i] = As[kk][ty * 8 + i];
            float4 b0 = *reinterpret_cast<float4*>(&Bs[kk][tx * 8]);
            float4 b1 = *reinterpret_cast<float4*>(&Bs[kk][tx * 8 + 4]);
            rb[0] = b0.x; rb[1] = b0.y; rb[2] = b0.z; rb[3] = b0.w;
            rb[4] = b1.x; rb[5] = b1.y; rb[6] = b1.z; rb[7] = b1.w;
#pragma unroll
            for (int i = 0; i < 8; i++)
#pragma unroll
                for (int j = 0; j < 8; j++)
                    acc[i][j] = fmaf(ra[i], rb[j], acc[i][j]);
        }
        __syncthreads();
    }

#pragma unroll
    for (int i = 0; i < 8; i++) {
        const int row = br * 128 + ty * 8 + i;
#pragma unroll
        for (int j = 0; j < 8; j++) {
            const int col = bc * 128 + tx * 8 + j;
            const float v = acc[i][j] + bias[col];
            if (mode == 0) {
                Cout[(size_t)row * N + col] = v;
            } else {
                const int b = row >> 11, s = row & 2047;
                const int h = col >> 6, d = col & 63;
                float* dst = (mode == 1) ? g_q : (mode == 2) ? g_k : g_v;
                dst[(((size_t)(b * 16 + h)) * S_LEN + s) * DEPTH + d] = v;
            }
        }
    }
}

// ============================================================
// Scores: logits[z,q,k] = dot(Qh[z,q,:], Kh[z,k,:]) * 0.125 + mask*1e-9
// grid (k_tiles=16, q_tiles=32, z=32); tile 64(q) x 128(k), depth 64.
// Smem d-major (48KB exactly).
// ============================================================
__global__ __launch_bounds__(256) void scores_kernel(
    const float* __restrict__ mask, float* __restrict__ Pext)
{
    float* P = Pext ? Pext : g_attn;
    __shared__ float Qs[64][64];    // [d][q]
    __shared__ float Ks[64][128];   // [d][k]

    const int tid = threadIdx.x;
    const int z  = blockIdx.z;
    const int q0 = blockIdx.y * 64;
    const int k0 = blockIdx.x * 128;
    const int b  = z >> 4;

    const float* Qb = g_q + ((size_t)z * S_LEN + q0) * DEPTH;
    const float* Kb = g_k + ((size_t)z * S_LEN + k0) * DEPTH;

    const int r  = tid >> 4;          // 0..15
    const int dc = (tid & 15) << 2;   // 0..60
#pragma unroll
    for (int p = 0; p < 4; p++) {
        float4 a = *reinterpret_cast<const float4*>(Qb + (size_t)(r + p * 16) * DEPTH + dc);
        Qs[dc + 0][r + p * 16] = a.x;
        Qs[dc + 1][r + p * 16] = a.y;
        Qs[dc + 2][r + p * 16] = a.z;
        Qs[dc + 3][r + p * 16] = a.w;
    }
#pragma unroll
    for (int p = 0; p < 8; p++) {
        float4 a = *reinterpret_cast<const float4*>(Kb + (size_t)(r + p * 16) * DEPTH + dc);
        Ks[dc + 0][r + p * 16] = a.x;
        Ks[dc + 1][r + p * 16] = a.y;
        Ks[dc + 2][r + p * 16] = a.z;
        Ks[dc + 3][r + p * 16] = a.w;
    }
    __syncthreads();

    const int ty = tid >> 4, tx = tid & 15;
    float acc[4][8];
#pragma unroll
    for (int i = 0; i < 4; i++)
#pragma unroll
        for (int j = 0; j < 8; j++) acc[i][j] = 0.0f;

#pragma unroll
    for (int d = 0; d < 64; d++) {
        float ra[4], rb[8];
#pragma unroll
        for (int i = 0; i < 4; i++) ra[i] = Qs[d][ty * 4 + i];
        float4 b0 = *reinterpret_cast<float4*>(&Ks[d][tx * 8]);
        float4 b1 = *reinterpret_cast<float4*>(&Ks[d][tx * 8 + 4]);
        rb[0] = b0.x; rb[1] = b0.y; rb[2] = b0.z; rb[3] = b0.w;
        rb[4] = b1.x; rb[5] = b1.y; rb[6] = b1.z; rb[7] = b1.w;
#pragma unroll
        for (int i = 0; i < 4; i++)
#pragma unroll
            for (int j = 0; j < 8; j++)
                acc[i][j] = fmaf(ra[i], rb[j], acc[i][j]);
    }

#pragma unroll
    for (int i = 0; i < 4; i++) {
        const int q = q0 + ty * 4 + i;
        const size_t prow = ((size_t)z * S_LEN + q) * S_LEN;
        const float* mrow = mask + ((size_t)b * S_LEN + q) * S_LEN;
#pragma unroll
        for (int j = 0; j < 8; j++) {
            const int k = k0 + tx * 8 + j;
            P[prow + k] = acc[i][j] * 0.125f + mrow[k] * 1e-9f;
        }
    }
}

// ============================================================
// Softmax in-place over last dim (2048). One block per row.
// ============================================================
__global__ __launch_bounds__(256) void softmax_kernel(float* __restrict__ Pext)
{
    float* P = Pext ? Pext : g_attn;
    const size_t base = (size_t)blockIdx.x * S_LEN;
    const int tid = threadIdx.x;

    float v[8];
#pragma unroll
    for (int i = 0; i < 8; i++) v[i] = P[base + i * 256 + tid];

    float m = v[0];
#pragma unroll
    for (int i = 1; i < 8; i++) m = fmaxf(m, v[i]);
#pragma unroll
    for (int o = 16; o > 0; o >>= 1) m = fmaxf(m, __shfl_xor_sync(0xffffffffu, m, o));

    __shared__ float redm[8];
    __shared__ float reds[8];
    if ((tid & 31) == 0) redm[tid >> 5] = m;
    __syncthreads();
    float mall = redm[0];
#pragma unroll
    for (int w = 1; w < 8; w++) mall = fmaxf(mall, redm[w]);

    float s = 0.0f;
#pragma unroll
    for (int i = 0; i < 8; i++) { v[i] = __expf(v[i] - mall); s += v[i]; }
#pragma unroll
    for (int o = 16; o > 0; o >>= 1) s += __shfl_xor_sync(0xffffffffu, s, o);
    if ((tid & 31) == 0) reds[tid >> 5] = s;
    __syncthreads();
    float sall = 0.0f;
#pragma unroll
    for (int w = 0; w < 8; w++) sall += reds[w];
    const float inv = 1.0f / sall;

#pragma unroll
    for (int i = 0; i < 8; i++) P[base + i * 256 + tid] = v[i] * inv;
}

// ============================================================
// ctx = attn @ V per (b,h), output into g_ctx [b*S+s][h*64+d].
// grid (q_tiles=16, z=32); tile 128(q) x 64(d), k-tile 32.
// ============================================================
__global__ __launch_bounds__(256) void ctx_kernel(const float* __restrict__ Pext)
{
    const float* P = Pext ? Pext : g_attn;
    __shared__ float Ps[128][32];   // [q][kc]
    __shared__ float Vs[32][64];    // [kc][d]

    const int tid = threadIdx.x;
    const int z  = blockIdx.y;
    const int q0 = blockIdx.x * 128;
    const float* Pb = P + ((size_t)z * S_LEN + q0) * S_LEN;
    const float* Vb = g_v + (size_t)z * S_LEN * DEPTH;

    const int ty = tid >> 4, tx = tid & 15;
    float acc[8][4];
#pragma unroll
    for (int i = 0; i < 8; i++)
#pragma unroll
        for (int j = 0; j < 4; j++) acc[i][j] = 0.0f;

    const int pqr = tid >> 3;           // 0..31
    const int pkc = (tid & 7) << 2;     // 0..28
    const int vvr = tid >> 4;           // 0..15
    const int vvc = (tid & 15) << 2;    // 0..60

    for (int kk0 = 0; kk0 < S_LEN; kk0 += 32) {
#pragma unroll
        for (int p = 0; p < 4; p++) {
            float4 a = *reinterpret_cast<const float4*>(
                Pb + (size_t)(pqr + p * 32) * S_LEN + kk0 + pkc);
            *reinterpret_cast<float4*>(&Ps[pqr + p * 32][pkc]) = a;
        }
#pragma unroll
        for (int p = 0; p < 2; p++) {
            float4 a = *reinterpret_cast<const float4*>(
                Vb + (size_t)(kk0 + vvr + p * 16) * DEPTH + vvc);
            *reinterpret_cast<float4*>(&Vs[vvr + p * 16][vvc]) = a;
        }
        __syncthreads();
#pragma unroll
        for (int kc = 0; kc < 32; kc++) {
            float ra[8];
#pragma unroll
            for (int i = 0; i < 8; i++) ra[i] = Ps[ty * 8 + i][kc];
            float4 b = *reinterpret_cast<float4*>(&Vs[kc][tx * 4]);
            float rb[4] = {b.x, b.y, b.z, b.w};
#pragma unroll
            for (int i = 0; i < 8; i++)
#pragma unroll
                for (int j = 0; j < 4; j++)
                    acc[i][j] = fmaf(ra[i], rb[j], acc[i][j]);
        }
        __syncthreads();
    }

    const int b = z >> 4, h = z & 15;
#pragma unroll
    for (int i = 0; i < 8; i++) {
        const int q = q0 + ty * 8 + i;
#pragma unroll
        for (int j = 0; j < 4; j++) {
            const int d = tx * 4 + j;
            g_ctx[((size_t)(b * S_LEN + q)) * DM + h * DEPTH + d] = acc[i][j];
        }
    }
}

// ============================================================
// launch
// ============================================================
extern "C" void kernel_launch(void* const* d_in, const int* in_sizes, int n_in,
                              void* d_out, int out_size)
{
    const float* q    = (const float*)d_in[0];
    const float* k    = (const float*)d_in[1];
    const float* v    = (const float*)d_in[2];
    const float* mask = (const float*)d_in[3];
    const float* wq   = (const float*)d_in[4];
    const float* bq   = (const float*)d_in[5];
    const float* wk   = (const float*)d_in[6];
    const float* bk   = (const float*)d_in[7];
    const float* wv   = (const float*)d_in[8];
    const float* bv   = (const float*)d_in[9];
    const float* wo   = (const float*)d_in[10];
    const float* bo   = (const float*)d_in[11];

    float* outp = (float*)d_out;
    const size_t osz = (size_t)out_size;

    // Reference returns (out, attn). Resolve destinations by out_size.
    float* attn_dst = nullptr;    // nullptr -> g_attn scratch inside kernels
    float* out_dst  = outp;       // nullptr -> g_out scratch inside kernel
    if (osz >= OUT_ELEMS + ATTN_ELEMS) {
        attn_dst = outp + OUT_ELEMS;
    } else if (osz == ATTN_ELEMS) {
        attn_dst = outp;
        out_dst  = nullptr;
    }

    const dim3 gThread(256);
    const dim3 gGemm(DM / 128, MROWS / 128);          // (8, 32)
    const dim3 gScore(S_LEN / 128, S_LEN / 64, BH);   // (16, 32, 32)
    const dim3 gSoft(BH * S_LEN);                     // 65536
    const dim3 gCtx(S_LEN / 128, BH);                 // (16, 32)

    // Projections (head-split outputs into g_q/g_k/g_v)
    gemm_bias_kernel<<<gGemm, gThread>>>(q, wq, bq, nullptr, MROWS, DM, DM, 1, 0);
    gemm_bias_kernel<<<gGemm, gThread>>>(k, wk, bk, nullptr, MROWS, DM, DM, 2, 0);
    gemm_bias_kernel<<<gGemm, gThread>>>(v, wv, bv, nullptr, MROWS, DM, DM, 3, 0);

    // Logits -> attn buffer
    scores_kernel<<<gScore, gThread>>>(mask, attn_dst);

    // Softmax in place
    softmax_kernel<<<gSoft, gThread>>>(attn_dst);

    // ctx = attn @ V -> g_ctx
    ctx_kernel<<<gCtx, gThread>>>(attn_dst);

    // out = ctx @ wo + bo
    gemm_bias_kernel<<<gGemm, gThread>>>(nullptr, wo, bo, out_dst, MROWS, DM, DM, 0, 1);
}

// round 3
// speedup vs baseline: 1.4672x; 1.4672x over previous
#include <cuda_runtime.h>
#include <cuda_bf16.h>
#include <cstdint>
#include <cstddef>

#define S_LEN 2048
#define DM    1024
#define BH    32
#define MROWS 4096
#define OUT_ELEMS  ((size_t)4194304)
#define ATTN_ELEMS ((size_t)134217728)

// ---- device scratch ----
__device__ float g_q[BH * S_LEN * 64];
__device__ float g_k[BH * S_LEN * 64];
__device__ float g_v[BH * S_LEN * 64];
__device__ float g_ctx[MROWS * DM];
__device__ float g_out[MROWS * DM];
__device__ float g_attn[BH * (size_t)S_LEN * S_LEN];
__device__ float g_part[16 * (size_t)65536];   // per-kblock row partial sums

#define SW128(o) (((uint32_t)(o)) ^ ((((uint32_t)(o)) >> 3) & 0x70u))

__device__ __forceinline__ uint32_t smem_u32(const void* p) {
    uint32_t a;
    asm("{ .reg .u64 t; cvta.to.shared.u64 t, %1; cvt.u32.u64 %0, t; }"
        : "=r"(a) : "l"(p));
    return a;
}

// ---- f32 -> bf16 hi/lo split, packed pairs ----
__device__ __forceinline__ void split_pair(float a, float b, uint32_t& hi, uint32_t& lo) {
    __nv_bfloat16 ha = __float2bfloat16(a), hb = __float2bfloat16(b);
    float ra = a - __bfloat162float(ha);
    float rb = b - __bfloat162float(hb);
    __nv_bfloat162 H; H.x = ha; H.y = hb;
    __nv_bfloat162 L; L.x = __float2bfloat16(ra); L.y = __float2bfloat16(rb);
    hi = *reinterpret_cast<uint32_t*>(&H);
    lo = *reinterpret_cast<uint32_t*>(&L);
}

#define LDSM_X4(r0, r1, r2, r3, addr) \
    asm volatile("ldmatrix.sync.aligned.m8n8.x4.shared.b16 {%0,%1,%2,%3}, [%4];" \
        : "=r"(r0), "=r"(r1), "=r"(r2), "=r"(r3) : "r"(addr))

#define MMA_BF16(c, a, b) \
    asm volatile("mma.sync.aligned.m16n8k16.row.col.f32.bf16.bf16.f32 " \
        "{%0,%1,%2,%3}, {%4,%5,%6,%7}, {%8,%9}, {%0,%1,%2,%3};" \
        : "+f"((c)[0]), "+f"((c)[1]), "+f"((c)[2]), "+f"((c)[3]) \
        : "r"((a)[0]), "r"((a)[1]), "r"((a)[2]), "r"((a)[3]), "r"((b)[0]), "r"((b)[1]))

// ============ warp MMA over one k64 stage (3-term split) ============
// A tiles: [rows][64 k] bf16 SW128 (128B rows); B tiles: [n-rows][64 k] same.
// Warp computes MF*16 rows x NF*8 cols. C layout: [MF][NF][4].
template <int MF, int NF>
__device__ __forceinline__ void mma_k64(uint32_t aHi, uint32_t aLo,
                                        uint32_t bHi, uint32_t bLo,
                                        int mwb, int nwb, int lane, float* C)
{
#pragma unroll
    for (int kc = 0; kc < 4; kc++) {
        uint32_t ah[MF][4], al[MF][4], bh[NF][2], bl[NF][2];
#pragma unroll
        for (int mi = 0; mi < MF; mi++) {
            const uint32_t off = SW128((uint32_t)((mwb + mi * 16 + (lane & 15)) * 128
                                                  + kc * 32 + (lane >> 4) * 16));
            LDSM_X4(ah[mi][0], ah[mi][1], ah[mi][2], ah[mi][3], aHi + off);
            LDSM_X4(al[mi][0], al[mi][1], al[mi][2], al[mi][3], aLo + off);
        }
#pragma unroll
        for (int nj = 0; nj < NF; nj += 2) {
            const int mat = lane >> 3;
            const int row = nwb + nj * 8 + ((mat >> 1) << 3) + (lane & 7);
            const uint32_t off = SW128((uint32_t)(row * 128 + kc * 32 + ((mat & 1) << 4)));
            LDSM_X4(bh[nj][0], bh[nj][1], bh[nj + 1][0], bh[nj + 1][1], bHi + off);
            LDSM_X4(bl[nj][0], bl[nj][1], bl[nj + 1][0], bl[nj + 1][1], bLo + off);
        }
#pragma unroll
        for (int mi = 0; mi < MF; mi++)
#pragma unroll
            for (int nj = 0; nj < NF; nj++) {
                float* c = C + (mi * NF + nj) * 4;
                MMA_BF16(c, ah[mi], bh[nj]);
                MMA_BF16(c, ah[mi], bl[nj]);
                MMA_BF16(c, al[mi], bh[nj]);
            }
    }
}

// ============ tile loaders (gmem fp32 -> regs -> split bf16 smem) ============
// A-style: 128 rows x 64 k, row stride rs.
__device__ __forceinline__ void loadA(const float* __restrict__ src, int rs, float sc,
                                      float4* v, int tid) {
    const int c4 = tid & 15, r0 = tid >> 4;
#pragma unroll
    for (int i = 0; i < 8; i++) {
        float4 a = *reinterpret_cast<const float4*>(src + (size_t)(r0 + i * 16) * rs + c4 * 4);
        v[i] = make_float4(a.x * sc, a.y * sc, a.z * sc, a.w * sc);
    }
}
__device__ __forceinline__ void stsA(char* hi, char* lo, const float4* v, int tid) {
    const int c4 = tid & 15, r0 = tid >> 4;
#pragma unroll
    for (int i = 0; i < 8; i++) {
        uint32_t h0, l0, h1, l1;
        split_pair(v[i].x, v[i].y, h0, l0);
        split_pair(v[i].z, v[i].w, h1, l1);
        const uint32_t off = SW128((uint32_t)((r0 + i * 16) * 128 + c4 * 8));
        *reinterpret_cast<uint2*>(hi + off) = make_uint2(h0, h1);
        *reinterpret_cast<uint2*>(lo + off) = make_uint2(l0, l1);
    }
}
// W transposed: B[n 128][k 64] from W[K,1024]
__device__ __forceinline__ void loadW(const float* __restrict__ W, int n0, int k0,
                                      float* v, int tid) {
    const int tn = tid & 127, kh = (tid >> 7) * 32;
    const float* p = W + (size_t)(k0 + kh) * 1024 + n0 + tn;
#pragma unroll
    for (int j = 0; j < 32; j++) v[j] = p[(size_t)j * 1024];
}
__device__ __forceinline__ void stsW(char* hi, char* lo, const float* v, int tid) {
    const int tn = tid & 127, kh = (tid >> 7) * 32;
#pragma unroll
    for (int j = 0; j < 32; j += 2) {
        uint32_t h, l;
        split_pair(v[j], v[j + 1], h, l);
        const uint32_t off = SW128((uint32_t)(tn * 128 + (kh + j) * 2));
        *reinterpret_cast<uint32_t*>(hi + off) = h;
        *reinterpret_cast<uint32_t*>(lo + off) = l;
    }
}
// V transposed: B[d 64][k 64] from Vz[s][64]
__device__ __forceinline__ void loadV(const float* __restrict__ Vz, int k0,
                                      float* v, int tid) {
    const int d = tid & 63, sb = (tid >> 6) * 16;
    const float* p = Vz + (size_t)(k0 + sb) * 64 + d;
#pragma unroll
    for (int j = 0; j < 16; j++) v[j] = p[j * 64];
}
__device__ __forceinline__ void stsV(char* hi, char* lo, const float* v, int tid) {
    const int d = tid & 63, sb = (tid >> 6) * 16;
#pragma unroll
    for (int j = 0; j < 16; j += 2) {
        uint32_t h, l;
        split_pair(v[j], v[j + 1], h, l);
        const uint32_t off = SW128((uint32_t)(d * 128 + (sb + j) * 2));
        *reinterpret_cast<uint32_t*>(hi + off) = h;
        *reinterpret_cast<uint32_t*>(lo + off) = l;
    }
}

// C frags -> padded smem bounce (conflict-free-ish stride)
template <int MF, int NF>
__device__ __forceinline__ void frag_to_bounce(float* sb, int stride, int mwb, int nwb,
                                               int lane, const float* C) {
#pragma unroll
    for (int mi = 0; mi < MF; mi++)
#pragma unroll
        for (int nj = 0; nj < NF; nj++) {
            const float* c = C + (mi * NF + nj) * 4;
            const int r = mwb + mi * 16 + (lane >> 2);
            const int cc = nwb + nj * 8 + (lane & 3) * 2;
            *reinterpret_cast<float2*>(sb + (size_t)r * stride + cc) = make_float2(c[0], c[1]);
            *reinterpret_cast<float2*>(sb + (size_t)(r + 8) * stride + cc) = make_float2(c[2], c[3]);
        }
}

// ================= projection / output GEMM =================
// C[4096,1024] = A@W + bias. mode 0: row-major (Cout or g_out);
// mode 1/2/3: head-split -> g_q/g_k/g_v. asel 1: A = g_ctx.
__global__ __launch_bounds__(256) void proj_mma(
    const float* __restrict__ Ain, const float* __restrict__ W,
    const float* __restrict__ bias, float* __restrict__ Cout, int mode, int asel)
{
    extern __shared__ char sm[];
    const float* A = asel ? g_ctx : Ain;
    float* C = Cout ? Cout : g_out;
    const int tid = threadIdx.x, wid = tid >> 5, lane = tid & 31;
    const int n0 = blockIdx.x * 128, m0 = blockIdx.y * 128;
    const int mwb = (wid & 1) * 64, nwb = (wid >> 1) * 32;

    float acc[64];
#pragma unroll
    for (int i = 0; i < 64; i++) acc[i] = 0.0f;

    char* b0 = sm;
    char* b1 = sm + 65536;

    float4 av[8];
    float wv[32];
    loadA(A + (size_t)m0 * 1024, 1024, 1.0f, av, tid);
    loadW(W, n0, 0, wv, tid);
    stsA(b0, b0 + 16384, av, tid);
    stsW(b0 + 32768, b0 + 49152, wv, tid);
    __syncthreads();

    for (int c = 0; c < 16; c++) {
        char* cur = (c & 1) ? b1 : b0;
        if (c < 15) {
            loadA(A + (size_t)m0 * 1024 + (c + 1) * 64, 1024, 1.0f, av, tid);
            loadW(W, n0, (c + 1) * 64, wv, tid);
        }
        mma_k64<4, 4>(smem_u32(cur), smem_u32(cur + 16384),
                      smem_u32(cur + 32768), smem_u32(cur + 49152),
                      mwb, nwb, lane, acc);
        if (c < 15) {
            char* nx = (c & 1) ? b0 : b1;
            stsA(nx, nx + 16384, av, tid);
            stsW(nx + 32768, nx + 49152, wv, tid);
        }
        __syncthreads();
    }

    float* sb = (float*)sm;
    frag_to_bounce<4, 4>(sb, 140, mwb, nwb, lane, acc);
    __syncthreads();

    const int row = tid >> 1, half = tid & 1;
    const int r = m0 + row;
    const float* sr = sb + (size_t)row * 140 + half * 64;
    const float* bp = bias + n0 + half * 64;
    if (mode == 0) {
        float* dst = C + (size_t)r * 1024 + n0 + half * 64;
#pragma unroll
        for (int j = 0; j < 16; j++) {
            float4 v = *reinterpret_cast<const float4*>(sr + j * 4);
            float4 b4 = *reinterpret_cast<const float4*>(bp + j * 4);
            v.x += b4.x; v.y += b4.y; v.z += b4.z; v.w += b4.w;
            *reinterpret_cast<float4*>(dst + j * 4) = v;
        }
    } else {
        const int bI = r >> 11, s = r & 2047;
        float* dst0 = (mode == 1) ? g_q : (mode == 2) ? g_k : g_v;
#pragma unroll
        for (int j = 0; j < 16; j++) {
            const int col = n0 + half * 64 + j * 4;
            const int h = col >> 6, d = col & 63;
            float4 v = *reinterpret_cast<const float4*>(sr + j * 4);
            float4 b4 = *reinterpret_cast<const float4*>(bp + j * 4);
            v.x += b4.x; v.y += b4.y; v.z += b4.z; v.w += b4.w;
            *reinterpret_cast<float4*>(dst0 + ((size_t)(bI * 16 + h) * 2048 + s) * 64 + d) = v;
        }
    }
}

// ================= scores: E = exp(QK^T/8 + mask*1e-9), partial row sums ======
__global__ __launch_bounds__(256) void scores_mma(
    const float* __restrict__ mask, float* __restrict__ Pext)
{
    extern __shared__ char sm[];
    float* P = Pext ? Pext : g_attn;
    const int tid = threadIdx.x, wid = tid >> 5, lane = tid & 31;
    const int z = blockIdx.z, q0 = blockIdx.y * 128, k0 = blockIdx.x * 128;
    const int b = z >> 4;
    const int mwb = (wid & 1) * 64, nwb = (wid >> 1) * 32;

    float acc[64];
#pragma unroll
    for (int i = 0; i < 64; i++) acc[i] = 0.0f;

    float4 av[8];
    loadA(g_q + ((size_t)z * 2048 + q0) * 64, 64, 0.125f, av, tid);
    stsA(sm, sm + 16384, av, tid);
    loadA(g_k + ((size_t)z * 2048 + k0) * 64, 64, 1.0f, av, tid);
    stsA(sm + 32768, sm + 49152, av, tid);
    __syncthreads();

    mma_k64<4, 4>(smem_u32(sm), smem_u32(sm + 16384),
                  smem_u32(sm + 32768), smem_u32(sm + 49152),
                  mwb, nwb, lane, acc);
    __syncthreads();

    float* sb = (float*)sm;
    frag_to_bounce<4, 4>(sb, 140, mwb, nwb, lane, acc);
    __syncthreads();

    const int row = tid >> 1, half = tid & 1;
    const int q = q0 + row;
    const float* sr = sb + (size_t)row * 140 + half * 64;
    const float* mrow = mask + ((size_t)b * 2048 + q) * 2048 + k0 + half * 64;
    float* prow = P + ((size_t)z * 2048 + q) * 2048 + k0 + half * 64;
    float s = 0.0f;
#pragma unroll
    for (int j = 0; j < 16; j++) {
        float4 v = *reinterpret_cast<const float4*>(sr + j * 4);
        float4 mk = *reinterpret_cast<const float4*>(mrow + j * 4);
        float e0 = __expf(v.x + mk.x * 1e-9f);
        float e1 = __expf(v.y + mk.y * 1e-9f);
        float e2 = __expf(v.z + mk.z * 1e-9f);
        float e3 = __expf(v.w + mk.w * 1e-9f);
        s += (e0 + e1) + (e2 + e3);
        *reinterpret_cast<float4*>(prow + j * 4) = make_float4(e0, e1, e2, e3);
    }
    s += __shfl_xor_sync(0xffffffffu, s, 1);
    if (half == 0)
        g_part[(size_t)blockIdx.x * 65536 + (size_t)z * 2048 + q] = s;
}

// ================= ctx = (E/rowsum) @ V; writes normalized attn in place =====
__global__ __launch_bounds__(256) void ctx_mma(float* __restrict__ Pext)
{
    extern __shared__ char sm[];
    __shared__ float sinv[128];
    float* P = Pext ? Pext : g_attn;
    const int tid = threadIdx.x, wid = tid >> 5, lane = tid & 31;
    const int z = blockIdx.y, q0 = blockIdx.x * 128;
    const int mwb = (wid & 3) * 32, nwb = (wid >> 2) * 32;

    if (tid < 128) {
        float s = 0.0f;
#pragma unroll
        for (int p = 0; p < 16; p++)
            s += g_part[(size_t)p * 65536 + (size_t)z * 2048 + q0 + tid];
        sinv[tid] = 1.0f / s;
    }
    __syncthreads();

    float acc[32];
#pragma unroll
    for (int i = 0; i < 32; i++) acc[i] = 0.0f;

    char* b0 = sm;
    char* b1 = sm + 49152;
    const float* Vz = g_v + (size_t)z * 2048 * 64;
    float* Pz = P + ((size_t)z * 2048 + q0) * 2048;

    const int c4 = tid & 15, r0 = tid >> 4;
    float4 av[8];
    float vv[16];

    // prologue chunk 0
#pragma unroll
    for (int i = 0; i < 8; i++)
        av[i] = *reinterpret_cast<const float4*>(Pz + (size_t)(r0 + i * 16) * 2048 + c4 * 4);
    loadV(Vz, 0, vv, tid);
    {
        char* hi = b0; char* lo = b0 + 16384;
#pragma unroll
        for (int i = 0; i < 8; i++) {
            const int r = r0 + i * 16;
            const float iv = sinv[r];
            float4 w = make_float4(av[i].x * iv, av[i].y * iv, av[i].z * iv, av[i].w * iv);
            *reinterpret_cast<float4*>(Pz + (size_t)r * 2048 + c4 * 4) = w;
            uint32_t h0, l0, h1, l1;
            split_pair(w.x, w.y, h0, l0);
            split_pair(w.z, w.w, h1, l1);
            const uint32_t off = SW128((uint32_t)(r * 128 + c4 * 8));
            *reinterpret_cast<uint2*>(hi + off) = make_uint2(h0, h1);
            *reinterpret_cast<uint2*>(lo + off) = make_uint2(l0, l1);
        }
        stsV(b0 + 32768, b0 + 40960, vv, tid);
    }
    __syncthreads();

    for (int c = 0; c < 32; c++) {
        char* cur = (c & 1) ? b1 : b0;
        if (c < 31) {
#pragma unroll
            for (int i = 0; i < 8; i++)
                av[i] = *reinterpret_cast<const float4*>(
                    Pz + (size_t)(r0 + i * 16) * 2048 + (c + 1) * 64 + c4 * 4);
            loadV(Vz, (c + 1) * 64, vv, tid);
        }
        mma_k64<2, 4>(smem_u32(cur), smem_u32(cur + 16384),
                      smem_u32(cur + 32768), smem_u32(cur + 40960),
                      mwb, nwb, lane, acc);
        if (c < 31) {
            char* nx = (c & 1) ? b0 : b1;
            char* hi = nx; char* lo = nx + 16384;
#pragma unroll
            for (int i = 0; i < 8; i++) {
                const int r = r0 + i * 16;
                const float iv = sinv[r];
                float4 w = make_float4(av[i].x * iv, av[i].y * iv, av[i].z * iv, av[i].w * iv);
                *reinterpret_cast<float4*>(Pz + (size_t)r * 2048 + (c + 1) * 64 + c4 * 4) = w;
                uint32_t h0, l0, h1, l1;
                split_pair(w.x, w.y, h0, l0);
                split_pair(w.z, w.w, h1, l1);
                const uint32_t off = SW128((uint32_t)(r * 128 + c4 * 8));
                *reinterpret_cast<uint2*>(hi + off) = make_uint2(h0, h1);
                *reinterpret_cast<uint2*>(lo + off) = make_uint2(l0, l1);
            }
            stsV(nx + 32768, nx + 40960, vv, tid);
        }
        __syncthreads();
    }

    float* sb = (float*)sm;
    frag_to_bounce<2, 4>(sb, 76, mwb, nwb, lane, acc);
    __syncthreads();

    const int row = tid >> 1, half = tid & 1;
    const int q = q0 + row;
    const int bb = z >> 4, h = z & 15;
    const float* sr = sb + (size_t)row * 76 + half * 32;
    float* dst = g_ctx + ((size_t)(bb * 2048 + q)) * 1024 + h * 64 + half * 32;
#pragma unroll
    for (int j = 0; j < 8; j++)
        *reinterpret_cast<float4*>(dst + j * 4) = *reinterpret_cast<const float4*>(sr + j * 4);
}

// ================= launch =================
extern "C" void kernel_launch(void* const* d_in, const int* in_sizes, int n_in,
                              void* d_out, int out_size)
{
    const float* q    = (const float*)d_in[0];
    const float* k    = (const float*)d_in[1];
    const float* v    = (const float*)d_in[2];
    const float* mask = (const float*)d_in[3];
    const float* wq   = (const float*)d_in[4];
    const float* bq   = (const float*)d_in[5];
    const float* wk   = (const float*)d_in[6];
    const float* bk   = (const float*)d_in[7];
    const float* wv   = (const float*)d_in[8];
    const float* bv   = (const float*)d_in[9];
    const float* wo   = (const float*)d_in[10];
    const float* bo   = (const float*)d_in[11];

    float* outp = (float*)d_out;
    const size_t osz = (size_t)out_size;

    float* attn_dst = nullptr;
    float* out_dst  = outp;
    if (osz >= OUT_ELEMS + ATTN_ELEMS) {
        attn_dst = outp + OUT_ELEMS;
    } else if (osz == ATTN_ELEMS) {
        attn_dst = outp;
        out_dst  = nullptr;
    }

    static bool attr_done = false;
    if (!attr_done) {
        cudaFuncSetAttribute(proj_mma,   cudaFuncAttributeMaxDynamicSharedMemorySize, 131072);
        cudaFuncSetAttribute(scores_mma, cudaFuncAttributeMaxDynamicSharedMemorySize, 71680);
        cudaFuncSetAttribute(ctx_mma,    cudaFuncAttributeMaxDynamicSharedMemorySize, 98304);
        attr_done = true;
    }

    const dim3 t(256);
    proj_mma<<<dim3(8, 32), t, 131072>>>(q, wq, bq, nullptr, 1, 0);
    proj_mma<<<dim3(8, 32), t, 131072>>>(k, wk, bk, nullptr, 2, 0);
    proj_mma<<<dim3(8, 32), t, 131072>>>(v, wv, bv, nullptr, 3, 0);

    scores_mma<<<dim3(16, 16, 32), t, 71680>>>(mask, attn_dst);
    ctx_mma<<<dim3(16, 32), t, 98304>>>(attn_dst);

    proj_mma<<<dim3(8, 32), t, 131072>>>(nullptr, wo, bo, out_dst, 0, 1);
}

// round 4
// speedup vs baseline: 2.6309x; 1.7931x over previous
#include <cuda_runtime.h>
#include <cuda_bf16.h>
#include <cstdint>
#include <cstddef>

#define S_LEN 2048
#define DM    1024
#define BH    32
#define MROWS 4096
#define OUT_ELEMS  ((size_t)4194304)
#define ATTN_ELEMS ((size_t)134217728)

// ---- device scratch ----
__device__ float g_q[BH * S_LEN * 64];
__device__ float g_k[BH * S_LEN * 64];
__device__ float g_v[BH * S_LEN * 64];
__device__ float g_ctx[MROWS * DM];
__device__ float g_out[MROWS * DM];
__device__ float g_attn[BH * (size_t)S_LEN * S_LEN];
__device__ float g_part[65536];   // full row sums of exp-scores

#define SW128(o) (((uint32_t)(o)) ^ ((((uint32_t)(o)) >> 3) & 0x70u))

__device__ __forceinline__ uint32_t smem_u32(const void* p) {
    uint32_t a;
    asm("{ .reg .u64 t; cvta.to.shared.u64 t, %1; cvt.u32.u64 %0, t; }"
        : "=r"(a) : "l"(p));
    return a;
}

// ---- f32 -> bf16 hi/lo split, packed pairs ----
__device__ __forceinline__ void split_pair(float a, float b, uint32_t& hi, uint32_t& lo) {
    __nv_bfloat16 ha = __float2bfloat16(a), hb = __float2bfloat16(b);
    float ra = a - __bfloat162float(ha);
    float rb = b - __bfloat162float(hb);
    __nv_bfloat162 H; H.x = ha; H.y = hb;
    __nv_bfloat162 L; L.x = __float2bfloat16(ra); L.y = __float2bfloat16(rb);
    hi = *reinterpret_cast<uint32_t*>(&H);
    lo = *reinterpret_cast<uint32_t*>(&L);
}

#define LDSM_X4(r0, r1, r2, r3, addr) \
    asm volatile("ldmatrix.sync.aligned.m8n8.x4.shared.b16 {%0,%1,%2,%3}, [%4];" \
        : "=r"(r0), "=r"(r1), "=r"(r2), "=r"(r3) : "r"(addr))

#define MMA_BF16(c, a, b) \
    asm volatile("mma.sync.aligned.m16n8k16.row.col.f32.bf16.bf16.f32 " \
        "{%0,%1,%2,%3}, {%4,%5,%6,%7}, {%8,%9}, {%0,%1,%2,%3};" \
        : "+f"((c)[0]), "+f"((c)[1]), "+f"((c)[2]), "+f"((c)[3]) \
        : "r"((a)[0]), "r"((a)[1]), "r"((a)[2]), "r"((a)[3]), "r"((b)[0]), "r"((b)[1]))

// ============ warp MMA over one k64 stage (3-term split) ============
template <int MF, int NF>
__device__ __forceinline__ void mma_k64(uint32_t aHi, uint32_t aLo,
                                        uint32_t bHi, uint32_t bLo,
                                        int mwb, int nwb, int lane, float* C)
{
#pragma unroll
    for (int kc = 0; kc < 4; kc++) {
        uint32_t ah[MF][4], al[MF][4], bh[NF][2], bl[NF][2];
#pragma unroll
        for (int mi = 0; mi < MF; mi++) {
            const uint32_t off = SW128((uint32_t)((mwb + mi * 16 + (lane & 15)) * 128
                                                  + kc * 32 + (lane >> 4) * 16));
            LDSM_X4(ah[mi][0], ah[mi][1], ah[mi][2], ah[mi][3], aHi + off);
            LDSM_X4(al[mi][0], al[mi][1], al[mi][2], al[mi][3], aLo + off);
        }
#pragma unroll
        for (int nj = 0; nj < NF; nj += 2) {
            const int mat = lane >> 3;
            const int row = nwb + nj * 8 + ((mat >> 1) << 3) + (lane & 7);
            const uint32_t off = SW128((uint32_t)(row * 128 + kc * 32 + ((mat & 1) << 4)));
            LDSM_X4(bh[nj][0], bh[nj][1], bh[nj + 1][0], bh[nj + 1][1], bHi + off);
            LDSM_X4(bl[nj][0], bl[nj][1], bl[nj + 1][0], bl[nj + 1][1], bLo + off);
        }
#pragma unroll
        for (int mi = 0; mi < MF; mi++)
#pragma unroll
            for (int nj = 0; nj < NF; nj++) {
                float* c = C + (mi * NF + nj) * 4;
                MMA_BF16(c, ah[mi], bh[nj]);
                MMA_BF16(c, ah[mi], bl[nj]);
                MMA_BF16(c, al[mi], bh[nj]);
            }
    }
}

// ============ tile loaders ============
// 128 rows x 64 k, row stride rs
__device__ __forceinline__ void loadA(const float* __restrict__ src, int rs, float sc,
                                      float4* v, int tid) {
    const int c4 = tid & 15, r0 = tid >> 4;
#pragma unroll
    for (int i = 0; i < 8; i++) {
        float4 a = *reinterpret_cast<const float4*>(src + (size_t)(r0 + i * 16) * rs + c4 * 4);
        v[i] = make_float4(a.x * sc, a.y * sc, a.z * sc, a.w * sc);
    }
}
__device__ __forceinline__ void stsA(char* hi, char* lo, const float4* v, int tid) {
    const int c4 = tid & 15, r0 = tid >> 4;
#pragma unroll
    for (int i = 0; i < 8; i++) {
        uint32_t h0, l0, h1, l1;
        split_pair(v[i].x, v[i].y, h0, l0);
        split_pair(v[i].z, v[i].w, h1, l1);
        const uint32_t off = SW128((uint32_t)((r0 + i * 16) * 128 + c4 * 8));
        *reinterpret_cast<uint2*>(hi + off) = make_uint2(h0, h1);
        *reinterpret_cast<uint2*>(lo + off) = make_uint2(l0, l1);
    }
}
// 64 rows x 64 k variants
__device__ __forceinline__ void loadA64(const float* __restrict__ src, int rs, float sc,
                                        float4* v, int tid) {
    const int c4 = tid & 15, r0 = tid >> 4;
#pragma unroll
    for (int i = 0; i < 4; i++) {
        float4 a = *reinterpret_cast<const float4*>(src + (size_t)(r0 + i * 16) * rs + c4 * 4);
        v[i] = make_float4(a.x * sc, a.y * sc, a.z * sc, a.w * sc);
    }
}
__device__ __forceinline__ void stsA64(char* hi, char* lo, const float4* v, int tid) {
    const int c4 = tid & 15, r0 = tid >> 4;
#pragma unroll
    for (int i = 0; i < 4; i++) {
        uint32_t h0, l0, h1, l1;
        split_pair(v[i].x, v[i].y, h0, l0);
        split_pair(v[i].z, v[i].w, h1, l1);
        const uint32_t off = SW128((uint32_t)((r0 + i * 16) * 128 + c4 * 8));
        *reinterpret_cast<uint2*>(hi + off) = make_uint2(h0, h1);
        *reinterpret_cast<uint2*>(lo + off) = make_uint2(l0, l1);
    }
}
// W transposed: B[n 128][k 64] from W[K,1024]
__device__ __forceinline__ void loadW(const float* __restrict__ W, int n0, int k0,
                                      float* v, int tid) {
    const int tn = tid & 127, kh = (tid >> 7) * 32;
    const float* p = W + (size_t)(k0 + kh) * 1024 + n0 + tn;
#pragma unroll
    for (int j = 0; j < 32; j++) v[j] = p[(size_t)j * 1024];
}
__device__ __forceinline__ void stsW(char* hi, char* lo, const float* v, int tid) {
    const int tn = tid & 127, kh = (tid >> 7) * 32;
#pragma unroll
    for (int j = 0; j < 32; j += 2) {
        uint32_t h, l;
        split_pair(v[j], v[j + 1], h, l);
        const uint32_t off = SW128((uint32_t)(tn * 128 + (kh + j) * 2));
        *reinterpret_cast<uint32_t*>(hi + off) = h;
        *reinterpret_cast<uint32_t*>(lo + off) = l;
    }
}
// V transposed 64x64: B[d 64][s 64] from Vz[s][64]
__device__ __forceinline__ void loadV64(const float* __restrict__ Vz, int k0,
                                        float* v, int tid) {
    const int d = tid & 63, sb = (tid >> 6) * 16;
    const float* p = Vz + (size_t)(k0 + sb) * 64 + d;
#pragma unroll
    for (int j = 0; j < 16; j++) v[j] = p[j * 64];
}
__device__ __forceinline__ void stsV64(char* hi, char* lo, const float* v, int tid) {
    const int d = tid & 63, sb = (tid >> 6) * 16;
#pragma unroll
    for (int j = 0; j < 16; j += 2) {
        uint32_t h, l;
        split_pair(v[j], v[j + 1], h, l);
        const uint32_t off = SW128((uint32_t)(d * 128 + (sb + j) * 2));
        *reinterpret_cast<uint32_t*>(hi + off) = h;
        *reinterpret_cast<uint32_t*>(lo + off) = l;
    }
}

// C frags -> padded smem bounce
template <int MF, int NF>
__device__ __forceinline__ void frag_to_bounce(float* sb, int stride, int mwb, int nwb,
                                               int lane, const float* C) {
#pragma unroll
    for (int mi = 0; mi < MF; mi++)
#pragma unroll
        for (int nj = 0; nj < NF; nj++) {
            const float* c = C + (mi * NF + nj) * 4;
            const int r = mwb + mi * 16 + (lane >> 2);
            const int cc = nwb + nj * 8 + (lane & 3) * 2;
            *reinterpret_cast<float2*>(sb + (size_t)r * stride + cc) = make_float2(c[0], c[1]);
            *reinterpret_cast<float2*>(sb + (size_t)(r + 8) * stride + cc) = make_float2(c[2], c[3]);
        }
}

// ================= projection / output GEMM (unchanged, known-good) =========
__global__ __launch_bounds__(256) void proj_mma(
    const float* __restrict__ Ain, const float* __restrict__ W,
    const float* __restrict__ bias, float* __restrict__ Cout, int mode, int asel)
{
    extern __shared__ char sm[];
    const float* A = asel ? g_ctx : Ain;
    float* C = Cout ? Cout : g_out;
    const int tid = threadIdx.x, wid = tid >> 5, lane = tid & 31;
    const int n0 = blockIdx.x * 128, m0 = blockIdx.y * 128;
    const int mwb = (wid & 1) * 64, nwb = (wid >> 1) * 32;

    float acc[64];
#pragma unroll
    for (int i = 0; i < 64; i++) acc[i] = 0.0f;

    char* b0 = sm;
    char* b1 = sm + 65536;

    float4 av[8];
    float wv[32];
    loadA(A + (size_t)m0 * 1024, 1024, 1.0f, av, tid);
    loadW(W, n0, 0, wv, tid);
    stsA(b0, b0 + 16384, av, tid);
    stsW(b0 + 32768, b0 + 49152, wv, tid);
    __syncthreads();

    for (int c = 0; c < 16; c++) {
        char* cur = (c & 1) ? b1 : b0;
        if (c < 15) {
            loadA(A + (size_t)m0 * 1024 + (c + 1) * 64, 1024, 1.0f, av, tid);
            loadW(W, n0, (c + 1) * 64, wv, tid);
        }
        mma_k64<4, 4>(smem_u32(cur), smem_u32(cur + 16384),
                      smem_u32(cur + 32768), smem_u32(cur + 49152),
                      mwb, nwb, lane, acc);
        if (c < 15) {
            char* nx = (c & 1) ? b0 : b1;
            stsA(nx, nx + 16384, av, tid);
            stsW(nx + 32768, nx + 49152, wv, tid);
        }
        __syncthreads();
    }

    float* sb = (float*)sm;
    frag_to_bounce<4, 4>(sb, 140, mwb, nwb, lane, acc);
    __syncthreads();

    const int row = tid >> 1, half = tid & 1;
    const int r = m0 + row;
    const float* sr = sb + (size_t)row * 140 + half * 64;
    const float* bp = bias + n0 + half * 64;
    if (mode == 0) {
        float* dst = C + (size_t)r * 1024 + n0 + half * 64;
#pragma unroll
        for (int j = 0; j < 16; j++) {
            float4 v = *reinterpret_cast<const float4*>(sr + j * 4);
            float4 b4 = *reinterpret_cast<const float4*>(bp + j * 4);
            v.x += b4.x; v.y += b4.y; v.z += b4.z; v.w += b4.w;
            *reinterpret_cast<float4*>(dst + j * 4) = v;
        }
    } else {
        const int bI = r >> 11, s = r & 2047;
        float* dst0 = (mode == 1) ? g_q : (mode == 2) ? g_k : g_v;
#pragma unroll
        for (int j = 0; j < 16; j++) {
            const int col = n0 + half * 64 + j * 4;
            const int h = col >> 6, d = col & 63;
            float4 v = *reinterpret_cast<const float4*>(sr + j * 4);
            float4 b4 = *reinterpret_cast<const float4*>(bp + j * 4);
            v.x += b4.x; v.y += b4.y; v.z += b4.z; v.w += b4.w;
            *reinterpret_cast<float4*>(dst0 + ((size_t)(bI * 16 + h) * 2048 + s) * 64 + d) = v;
        }
    }
}

// ================= scores v2: E = exp(QK^T/8 + mask*1e-9) ====================
// grid (32 q-tiles of 64, 32 z). Q persistent in smem; loop 16 k-tiles of 128.
// Register epilogue, direct gmem writes, full row-sums -> g_part.
__global__ __launch_bounds__(256, 2) void scores_mma(
    const float* __restrict__ mask, float* __restrict__ Pext)
{
    extern __shared__ char sm[];
    float* P = Pext ? Pext : g_attn;
    const int tid = threadIdx.x, wid = tid >> 5, lane = tid & 31;
    const int q0 = blockIdx.x * 64, z = blockIdx.y;
    const int b = z >> 4;
    const int mwb = (wid & 1) * 32, nwb = (wid >> 1) * 32;

    char* Qhi = sm;            // 8KB
    char* Qlo = sm + 8192;     // 8KB
    char* Khi = sm + 16384;    // 16KB
    char* Klo = sm + 32768;    // 16KB
    float* sred = (float*)(sm + 49152);   // [64][4]

    // persistent Q tile (scale 1/8 folded)
    {
        float4 qv[4];
        loadA64(g_q + ((size_t)z * 2048 + q0) * 64, 64, 0.125f, qv, tid);
        stsA64(Qhi, Qlo, qv, tid);
    }
    // K tile 0
    float4 av[8];
    loadA(g_k + (size_t)z * 2048 * 64, 64, 1.0f, av, tid);
    stsA(Khi, Klo, av, tid);
    __syncthreads();

    float srow[4] = {0.0f, 0.0f, 0.0f, 0.0f};
    float acc[32];

    for (int kt = 0; kt < 16; kt++) {
#pragma unroll
        for (int i = 0; i < 32; i++) acc[i] = 0.0f;
        if (kt < 15)
            loadA(g_k + ((size_t)z * 2048 + (kt + 1) * 128) * 64, 64, 1.0f, av, tid);

        mma_k64<2, 4>(smem_u32(Qhi), smem_u32(Qlo), smem_u32(Khi), smem_u32(Klo),
                      mwb, nwb, lane, acc);

        // register epilogue: exp + mask + direct store + rowsum
        const int kcol0 = kt * 128;
#pragma unroll
        for (int mi = 0; mi < 2; mi++)
#pragma unroll
            for (int h = 0; h < 2; h++) {
                const int q = q0 + mwb + mi * 16 + (lane >> 2) + h * 8;
                const float* mrow = mask + ((size_t)b * 2048 + q) * 2048 + kcol0;
                float* prow = P + ((size_t)z * 2048 + q) * 2048 + kcol0;
                float rs = 0.0f;
#pragma unroll
                for (int nj = 0; nj < 4; nj++) {
                    const float* c = acc + (mi * 4 + nj) * 4 + h * 2;
                    const int col = nwb + nj * 8 + (lane & 3) * 2;
                    float2 mk = *reinterpret_cast<const float2*>(mrow + col);
                    float e0 = __expf(c[0] + mk.x * 1e-9f);
                    float e1 = __expf(c[1] + mk.y * 1e-9f);
                    *reinterpret_cast<float2*>(prow + col) = make_float2(e0, e1);
                    rs += e0 + e1;
                }
                srow[mi * 2 + h] += rs;
            }

        __syncthreads();
        if (kt < 15) stsA(Khi, Klo, av, tid);
        __syncthreads();
    }

    // reduce row sums: lanes sharing a row differ only in (lane&3)
#pragma unroll
    for (int t = 0; t < 4; t++) {
        srow[t] += __shfl_xor_sync(0xffffffffu, srow[t], 1);
        srow[t] += __shfl_xor_sync(0xffffffffu, srow[t], 2);
    }
    if ((lane & 3) == 0) {
#pragma unroll
        for (int mi = 0; mi < 2; mi++)
#pragma unroll
            for (int h = 0; h < 2; h++) {
                const int rl = mwb + mi * 16 + (lane >> 2) + h * 8;
                sred[rl * 4 + (wid >> 1)] = srow[mi * 2 + h];
            }
    }
    __syncthreads();
    if (tid < 64) {
        g_part[(size_t)z * 2048 + q0 + tid] =
            sred[tid * 4] + sred[tid * 4 + 1] + sred[tid * 4 + 2] + sred[tid * 4 + 3];
    }
}

// ================= ctx v2 = (E/rowsum) @ V; normalizes attn in place =========
// grid (32 q-tiles of 64, 32 z); loops 32 s-chunks of 64.
__global__ __launch_bounds__(256, 2) void ctx_mma(float* __restrict__ Pext)
{
    extern __shared__ char sm[];
    float* P = Pext ? Pext : g_attn;
    const int tid = threadIdx.x, wid = tid >> 5, lane = tid & 31;
    const int q0 = blockIdx.x * 64, z = blockIdx.y;
    const int mwb = (wid & 1) * 32, nwb = (wid >> 1) * 16;

    char* Phi = sm;            // 8KB
    char* Plo = sm + 8192;
    char* Vhi = sm + 16384;
    char* Vlo = sm + 24576;
    float* sinv = (float*)(sm + 32768);   // [64]

    if (tid < 64) sinv[tid] = 1.0f / g_part[(size_t)z * 2048 + q0 + tid];
    __syncthreads();

    const float* Vz = g_v + (size_t)z * 2048 * 64;
    float* Pz = P + ((size_t)z * 2048 + q0) * 2048;

    float acc[16];
#pragma unroll
    for (int i = 0; i < 16; i++) acc[i] = 0.0f;

    const int c4 = tid & 15, r0 = tid >> 4;
    float4 av[4];
    float vv[16];

    // prologue: chunk 0
#pragma unroll
    for (int i = 0; i < 4; i++)
        av[i] = *reinterpret_cast<const float4*>(Pz + (size_t)(r0 + i * 16) * 2048 + c4 * 4);
    loadV64(Vz, 0, vv, tid);
#pragma unroll
    for (int i = 0; i < 4; i++) {
        const int r = r0 + i * 16;
        const float iv = sinv[r];
        float4 w = make_float4(av[i].x * iv, av[i].y * iv, av[i].z * iv, av[i].w * iv);
        *reinterpret_cast<float4*>(Pz + (size_t)r * 2048 + c4 * 4) = w;
        uint32_t h0, l0, h1, l1;
        split_pair(w.x, w.y, h0, l0);
        split_pair(w.z, w.w, h1, l1);
        const uint32_t off = SW128((uint32_t)(r * 128 + c4 * 8));
        *reinterpret_cast<uint2*>(Phi + off) = make_uint2(h0, h1);
        *reinterpret_cast<uint2*>(Plo + off) = make_uint2(l0, l1);
    }
    stsV64(Vhi, Vlo, vv, tid);
    __syncthreads();

    for (int c = 0; c < 32; c++) {
        if (c < 31) {
#pragma unroll
            for (int i = 0; i < 4; i++)
                av[i] = *reinterpret_cast<const float4*>(
                    Pz + (size_t)(r0 + i * 16) * 2048 + (c + 1) * 64 + c4 * 4);
            loadV64(Vz, (c + 1) * 64, vv, tid);
        }
        mma_k64<2, 2>(smem_u32(Phi), smem_u32(Plo), smem_u32(Vhi), smem_u32(Vlo),
                      mwb, nwb, lane, acc);
        __syncthreads();
        if (c < 31) {
#pragma unroll
            for (int i = 0; i < 4; i++) {
                const int r = r0 + i * 16;
                const float iv = sinv[r];
                float4 w = make_float4(av[i].x * iv, av[i].y * iv, av[i].z * iv, av[i].w * iv);
                *reinterpret_cast<float4*>(Pz + (size_t)r * 2048 + (c + 1) * 64 + c4 * 4) = w;
                uint32_t h0, l0, h1, l1;
                split_pair(w.x, w.y, h0, l0);
                split_pair(w.z, w.w, h1, l1);
                const uint32_t off = SW128((uint32_t)(r * 128 + c4 * 8));
                *reinterpret_cast<uint2*>(Phi + off) = make_uint2(h0, h1);
                *reinterpret_cast<uint2*>(Plo + off) = make_uint2(l0, l1);
            }
            stsV64(Vhi, Vlo, vv, tid);
        }
        __syncthreads();
    }

    // direct fragment -> g_ctx
    const int bb = z >> 4, hh = z & 15;
#pragma unroll
    for (int mi = 0; mi < 2; mi++)
#pragma unroll
        for (int h = 0; h < 2; h++) {
            const int q = q0 + mwb + mi * 16 + (lane >> 2) + h * 8;
            float* dst = g_ctx + ((size_t)(bb * 2048 + q)) * 1024 + hh * 64;
#pragma unroll
            for (int nj = 0; nj < 2; nj++) {
                const float* cc = acc + (mi * 2 + nj) * 4 + h * 2;
                const int col = nwb + nj * 8 + (lane & 3) * 2;
                *reinterpret_cast<float2*>(dst + col) = make_float2(cc[0], cc[1]);
            }
        }
}

// ================= launch =================
extern "C" void kernel_launch(void* const* d_in, const int* in_sizes, int n_in,
                              void* d_out, int out_size)
{
    const float* q    = (const float*)d_in[0];
    const float* k    = (const float*)d_in[1];
    const float* v    = (const float*)d_in[2];
    const float* mask = (const float*)d_in[3];
    const float* wq   = (const float*)d_in[4];
    const float* bq   = (const float*)d_in[5];
    const float* wk   = (const float*)d_in[6];
    const float* bk   = (const float*)d_in[7];
    const float* wv   = (const float*)d_in[8];
    const float* bv   = (const float*)d_in[9];
    const float* wo   = (const float*)d_in[10];
    const float* bo   = (const float*)d_in[11];

    float* outp = (float*)d_out;
    const size_t osz = (size_t)out_size;

    float* attn_dst = nullptr;
    float* out_dst  = outp;
    if (osz >= OUT_ELEMS + ATTN_ELEMS) {
        attn_dst = outp + OUT_ELEMS;
    } else if (osz == ATTN_ELEMS) {
        attn_dst = outp;
        out_dst  = nullptr;
    }

    static bool attr_done = false;
    if (!attr_done) {
        cudaFuncSetAttribute(proj_mma,   cudaFuncAttributeMaxDynamicSharedMemorySize, 131072);
        cudaFuncSetAttribute(scores_mma, cudaFuncAttributeMaxDynamicSharedMemorySize, 50176);
        cudaFuncSetAttribute(ctx_mma,    cudaFuncAttributeMaxDynamicSharedMemorySize, 33024);
        attr_done = true;
    }

    const dim3 t(256);
    proj_mma<<<dim3(8, 32), t, 131072>>>(q, wq, bq, nullptr, 1, 0);
    proj_mma<<<dim3(8, 32), t, 131072>>>(k, wk, bk, nullptr, 2, 0);
    proj_mma<<<dim3(8, 32), t, 131072>>>(v, wv, bv, nullptr, 3, 0);

    scores_mma<<<dim3(32, 32), t, 50176>>>(mask, attn_dst);
    ctx_mma<<<dim3(32, 32), t, 33024>>>(attn_dst);

    proj_mma<<<dim3(8, 32), t, 131072>>>(nullptr, wo, bo, out_dst, 0, 1);
}